// round 6
// baseline (speedup 1.0000x reference)
#include <cuda_runtime.h>
#include <cstdint>

// ---------------------------------------------------------------------------
// out[b] = sum_{n,p} (Agg_b^2)[n,p] * (x_b[p] . t_n)
//        + sum_n rowsum(Agg_b)[n] * s_n  +  c1
//
// Precompute (fused single kernel, soft grid barriers):
//   p1 = Wl3 . wl4
//   q  = Wl2 . p1 + wl4
//   M  = Wl1 . q  + wl4
//   c0 = bl1.q + bl2.p1 + bl3.wl4 + bl4
//   v_n = W2 @ M_n ; t_n = W1 @ v_n ; s_n = b1.v_n ; c1 = c0 + sum_n b2.M_n
// ---------------------------------------------------------------------------

__device__ float g_p1[256];
__device__ float g_q[256];
__device__ float g_M[256];
__device__ float g_TSC[61];   // T[56], s[4], c1
__device__ int   g_bar;       // monotonic ticket counter (never reset: replay-safe)

__device__ __forceinline__ void l2_prefetch(const void* p) {
    asm volatile("prefetch.global.L2 [%0];" :: "l"(p));
}

// Reset-free grid barrier: tickets are contiguous 32-aligned ranges per stage,
// so target = (ticket & ~31) + 32 works across graph replays without reset.
__device__ __forceinline__ void gridbar() {
    __syncthreads();
    if (threadIdx.x == 0) {
        __threadfence();
        int t = atomicAdd(&g_bar, 1);
        int target = (t & ~31) + 32;
        while ((*(volatile int*)&g_bar) - target < 0) { }
        __threadfence();
    }
    __syncthreads();
}

__global__ __launch_bounds__(256)
void precompute(const float* __restrict__ W1, const float* __restrict__ b1,
                const float* __restrict__ W2, const float* __restrict__ b2,
                const float* __restrict__ Wl1, const float* __restrict__ bl1,
                const float* __restrict__ Wl2, const float* __restrict__ bl2,
                const float* __restrict__ Wl3, const float* __restrict__ bl3,
                const float* __restrict__ wl4, const float* __restrict__ bl4)
{
    int tid = threadIdx.x, wid = tid >> 5, lane = tid & 31;
    int gtid = blockIdx.x * 256 + tid;

    // L2-prefetch the weights needed by later stages (one 128B line/thread),
    // overlapped with stage-0's cold DRAM reads of Wl3.
    if (gtid < 2048)      l2_prefetch(Wl2 + (size_t)gtid * 32);
    else if (gtid < 4096) l2_prefetch(Wl1 + (size_t)(gtid - 2048) * 32);
    else if (gtid < 4352) l2_prefetch(W2  + (size_t)(gtid - 4096) * 32);
    else if (gtid < 4408) l2_prefetch(W1  + (size_t)(gtid - 4352) * 32);

    int r = blockIdx.x * 8 + wid;   // warp-per-row, rows 0..255

    // ---- stage 0: p1 = Wl3 . wl4
    {
        const float* row = Wl3 + (size_t)r * 256;
        float a = 0.f;
        #pragma unroll
        for (int k = 0; k < 8; k++) a += row[lane + 32 * k] * wl4[lane + 32 * k];
        #pragma unroll
        for (int o = 16; o > 0; o >>= 1) a += __shfl_xor_sync(0xFFFFFFFFu, a, o);
        if (lane == 0) g_p1[r] = a;
    }
    gridbar();

    // ---- stage 1: q = Wl2 . p1 + wl4
    {
        const float* row = Wl2 + (size_t)r * 256;
        float a = 0.f;
        #pragma unroll
        for (int k = 0; k < 8; k++) a += row[lane + 32 * k] * g_p1[lane + 32 * k];
        #pragma unroll
        for (int o = 16; o > 0; o >>= 1) a += __shfl_xor_sync(0xFFFFFFFFu, a, o);
        if (lane == 0) g_q[r] = a + wl4[r];
    }
    gridbar();

    // ---- stage 2: M = Wl1 . q + wl4
    {
        const float* row = Wl1 + (size_t)r * 256;
        float a = 0.f;
        #pragma unroll
        for (int k = 0; k < 8; k++) a += row[lane + 32 * k] * g_q[lane + 32 * k];
        #pragma unroll
        for (int o = 16; o > 0; o >>= 1) a += __shfl_xor_sync(0xFFFFFFFFu, a, o);
        if (lane == 0) g_M[r] = a + wl4[r];
    }
    gridbar();

    // ---- finalize (block 0 only; everything now L2-warm)
    if (blockIdx.x != 0) return;

    __shared__ float sM[256];
    __shared__ float sV[512];
    __shared__ float sRed[8];
    int t = tid;

    sM[t] = g_M[t];
    float contrib = bl1[t] * g_q[t] + bl2[t] * g_p1[t] + bl3[t] * wl4[t];
    __syncthreads();
    if (t < 64)
        contrib += b2[t] * (sM[t] + sM[64 + t] + sM[128 + t] + sM[192 + t]);
    #pragma unroll
    for (int o = 16; o > 0; o >>= 1) contrib += __shfl_xor_sync(0xFFFFFFFFu, contrib, o);
    if (lane == 0) sRed[wid] = contrib;

    // V[n*128+k] = W2[k,:] . M_n   (2 outputs/thread)
    #pragma unroll
    for (int rep = 0; rep < 2; rep++) {
        int o = t + rep * 256;
        int n = o >> 7, k = o & 127;
        const float4* w4 = (const float4*)(W2 + (size_t)k * 64);
        const float4* m4 = (const float4*)(sM + n * 64);
        float a = 0.f;
        #pragma unroll
        for (int j = 0; j < 16; j++) {
            float4 w = w4[j], mm = m4[j];
            a += w.x * mm.x + w.y * mm.y + w.z * mm.z + w.w * mm.w;
        }
        sV[o] = a;
    }
    __syncthreads();

    // T/s/c1: warp wid handles rows wid*8 .. wid*8+7 (61 rows total)
    float4 wv[8];
    int    nn[8];
    #pragma unroll
    for (int j = 0; j < 8; j++) {
        int rr = wid * 8 + j;
        if (rr < 56)      { wv[j] = ((const float4*)(W1 + (size_t)(rr % 14) * 128))[lane]; nn[j] = rr / 14; }
        else if (rr < 60) { wv[j] = ((const float4*)b1)[lane];                              nn[j] = rr - 56; }
        else              { wv[j] = make_float4(0.f, 0.f, 0.f, 0.f);                        nn[j] = 0; }
    }
    #pragma unroll
    for (int j = 0; j < 8; j++) {
        int rr = wid * 8 + j;
        if (rr < 60) {
            float4 vv = ((const float4*)(sV + nn[j] * 128))[lane];
            float a = wv[j].x * vv.x + wv[j].y * vv.y + wv[j].z * vv.z + wv[j].w * vv.w;
            #pragma unroll
            for (int o = 16; o > 0; o >>= 1) a += __shfl_xor_sync(0xFFFFFFFFu, a, o);
            if (lane == 0) g_TSC[rr] = a;
        } else if (rr == 60 && lane == 0) {
            float c = bl4[0];
            #pragma unroll
            for (int q = 0; q < 8; q++) c += sRed[q];
            g_TSC[60] = c;
        }
    }
}

// ---- main kernel: 128 threads/block, shared-staged fully-coalesced loads
#define TPB 128
#define XS 57
#define ES 25

__global__ __launch_bounds__(TPB)
void gcn_main(const float* __restrict__ x, const int* __restrict__ eidx,
              float* __restrict__ out)
{
    __shared__ float sx[TPB * XS];
    __shared__ int   se[TPB * ES];
    __shared__ float sT[64];
    int tid = threadIdx.x;

    const float4* Xg = (const float4*)x + (size_t)blockIdx.x * TPB * 14;
    const int4*   Eg = (const int4*)eidx + (size_t)blockIdx.x * TPB * 6;
    float4 xv[14];
    int4   ev[6];
    #pragma unroll
    for (int i = 0; i < 14; i++) xv[i] = Xg[i * TPB + tid];
    #pragma unroll
    for (int i = 0; i < 6; i++)  ev[i] = Eg[i * TPB + tid];
    if (tid < 61) sT[tid] = g_TSC[tid];
    #pragma unroll
    for (int i = 0; i < 14; i++) {
        int idx4 = i * TPB + tid;
        int s = idx4 / 14, j = idx4 % 14;
        float* dst = sx + s * XS + j * 4;
        dst[0] = xv[i].x; dst[1] = xv[i].y; dst[2] = xv[i].z; dst[3] = xv[i].w;
    }
    #pragma unroll
    for (int i = 0; i < 6; i++) {
        int i4 = i * TPB + tid;
        int s = i4 / 6, r = i4 % 6;
        int* dst = se + s * ES + r * 4;
        dst[0] = ev[i].x; dst[1] = ev[i].y; dst[2] = ev[i].z; dst[3] = ev[i].w;
    }
    __syncthreads();

    const int* me = se + tid * ES;
    unsigned h0 = 1u + (1u << 20);         // self loops: codes 0, 5
    unsigned h1 = (1u << 8) + (1u << 28);  // codes 10, 15
    #pragma unroll
    for (int e = 0; e < 12; e++) {
        int code = (me[12 + e] << 2) | me[e];
        unsigned inc = 1u << ((code & 7) << 2);
        if (code & 8) h1 += inc; else h0 += inc;
    }
    float c[16];
    #pragma unroll
    for (int qd = 0; qd < 8; qd++) {
        c[qd]     = (float)((h0 >> (qd * 4)) & 15u);
        c[qd + 8] = (float)((h1 >> (qd * 4)) & 15u);
    }
    float dinv[4];
    #pragma unroll
    for (int d = 0; d < 4; d++)
        dinv[d] = rsqrtf(c[4*d] + c[4*d+1] + c[4*d+2] + c[4*d+3]);
    float A[16];
    #pragma unroll
    for (int d = 0; d < 4; d++)
        #pragma unroll
        for (int s = 0; s < 4; s++)
            A[d*4+s] = c[d*4+s] * dinv[d] * dinv[s];
    float A2[16], R[4];
    #pragma unroll
    for (int n = 0; n < 4; n++) {
        R[n] = A[n*4] + A[n*4+1] + A[n*4+2] + A[n*4+3];
        #pragma unroll
        for (int p = 0; p < 4; p++) {
            A2[n*4+p] = A[n*4+0] * A[0*4+p] + A[n*4+1] * A[1*4+p]
                      + A[n*4+2] * A[2*4+p] + A[n*4+3] * A[3*4+p];
        }
    }

    const float* mx = sx + tid * XS;
    float d[16];
    #pragma unroll
    for (int i = 0; i < 16; i++) d[i] = 0.f;
    #pragma unroll
    for (int f = 0; f < 14; f++) {
        float x0 = mx[f], x1 = mx[14+f], x2 = mx[28+f], x3 = mx[42+f];
        float t0 = sT[f], t1 = sT[14+f], t2 = sT[28+f], t3 = sT[42+f];
        d[0]  += x0*t0; d[1]  += x0*t1; d[2]  += x0*t2; d[3]  += x0*t3;
        d[4]  += x1*t0; d[5]  += x1*t1; d[6]  += x1*t2; d[7]  += x1*t3;
        d[8]  += x2*t0; d[9]  += x2*t1; d[10] += x2*t2; d[11] += x2*t3;
        d[12] += x3*t0; d[13] += x3*t1; d[14] += x3*t2; d[15] += x3*t3;
    }
    float acc = sT[60] + R[0]*sT[56] + R[1]*sT[57] + R[2]*sT[58] + R[3]*sT[59];
    #pragma unroll
    for (int n = 0; n < 4; n++)
        #pragma unroll
        for (int p = 0; p < 4; p++)
            acc += A2[n*4+p] * d[p*4+n];

    out[blockIdx.x * TPB + tid] = acc;
}

extern "C" void kernel_launch(void* const* d_in, const int* in_sizes, int n_in,
                              void* d_out, int out_size)
{
    const float* x   = (const float*)d_in[0];
    const int*   ei  = (const int*)  d_in[1];
    const float* W1  = (const float*)d_in[2];
    const float* b1  = (const float*)d_in[3];
    const float* W2  = (const float*)d_in[4];
    const float* b2  = (const float*)d_in[5];
    const float* Wl1 = (const float*)d_in[6];
    const float* bl1 = (const float*)d_in[7];
    const float* Wl2 = (const float*)d_in[8];
    const float* bl2 = (const float*)d_in[9];
    const float* Wl3 = (const float*)d_in[10];
    const float* bl3 = (const float*)d_in[11];
    const float* wl4 = (const float*)d_in[12];
    const float* bl4 = (const float*)d_in[13];

    int B = in_sizes[0] / 56;   // 262144

    precompute<<<32, 256>>>(W1, b1, W2, b2, Wl1, bl1, Wl2, bl2, Wl3, bl3, wl4, bl4);
    gcn_main<<<B / TPB, TPB>>>(x, ei, (float*)d_out);
}

// round 7
// speedup vs baseline: 1.0480x; 1.0480x over previous
#include <cuda_runtime.h>
#include <cstdint>

// ---------------------------------------------------------------------------
// out[b] = sum_{n,p} (Agg_b^2)[n,p] * (x_b[p] . t_n)
//        + sum_n rowsum(Agg_b)[n] * s_n  +  c1
// Precompute (fused single kernel, soft grid barriers):
//   p1 = Wl3.wl4 ; q = Wl2.p1 + wl4 ; M = Wl1.q + wl4
//   c0 = bl1.q + bl2.p1 + bl3.wl4 + bl4
//   v_n = W2 @ M_n ; t_n = W1 @ v_n ; s_n = b1.v_n ; c1 = c0 + sum_n b2.M_n
// ---------------------------------------------------------------------------

__device__ float g_p1[256];
__device__ float g_q[256];
__device__ float g_M[256];
__device__ float g_TSC[61];   // T[56], s[4], c1
__device__ int   g_bar;       // monotonic ticket counter (replay-safe, no reset)

__device__ __forceinline__ void l2_prefetch(const void* p) {
    asm volatile("prefetch.global.L2 [%0];" :: "l"(p));
}

__device__ __forceinline__ void gridbar() {
    __syncthreads();
    if (threadIdx.x == 0) {
        __threadfence();
        int t = atomicAdd(&g_bar, 1);
        int target = (t & ~31) + 32;
        while ((*(volatile int*)&g_bar) - target < 0) { }
        __threadfence();
    }
    __syncthreads();
}

// ---- packed f32x2 helpers (Blackwell FFMA2 path)
__device__ __forceinline__ unsigned long long pack2(float lo, float hi) {
    unsigned long long r;
    asm("mov.b64 %0, {%1, %2};" : "=l"(r) : "f"(lo), "f"(hi));
    return r;
}
__device__ __forceinline__ void fma2(unsigned long long& d,
                                     unsigned long long a, unsigned long long b) {
    asm("fma.rn.f32x2 %0, %1, %2, %0;" : "+l"(d) : "l"(a), "l"(b));
}
__device__ __forceinline__ float unpack_sum(unsigned long long v) {
    float lo, hi;
    asm("mov.b64 {%0, %1}, %2;" : "=f"(lo), "=f"(hi) : "l"(v));
    return lo + hi;
}

__global__ __launch_bounds__(256)
void precompute(const float* __restrict__ W1, const float* __restrict__ b1,
                const float* __restrict__ W2, const float* __restrict__ b2,
                const float* __restrict__ Wl1, const float* __restrict__ bl1,
                const float* __restrict__ Wl2, const float* __restrict__ bl2,
                const float* __restrict__ Wl3, const float* __restrict__ bl3,
                const float* __restrict__ wl4, const float* __restrict__ bl4)
{
    int tid = threadIdx.x, wid = tid >> 5, lane = tid & 31;
    int gtid = blockIdx.x * 256 + tid;

    if (gtid < 2048)      l2_prefetch(Wl2 + (size_t)gtid * 32);
    else if (gtid < 4096) l2_prefetch(Wl1 + (size_t)(gtid - 2048) * 32);
    else if (gtid < 4352) l2_prefetch(W2  + (size_t)(gtid - 4096) * 32);
    else if (gtid < 4408) l2_prefetch(W1  + (size_t)(gtid - 4352) * 32);

    int r = blockIdx.x * 8 + wid;   // warp-per-row, rows 0..255

    {   // stage 0: p1 = Wl3 . wl4
        const float* row = Wl3 + (size_t)r * 256;
        float a = 0.f;
        #pragma unroll
        for (int k = 0; k < 8; k++) a += row[lane + 32 * k] * wl4[lane + 32 * k];
        #pragma unroll
        for (int o = 16; o > 0; o >>= 1) a += __shfl_xor_sync(0xFFFFFFFFu, a, o);
        if (lane == 0) g_p1[r] = a;
    }
    gridbar();
    {   // stage 1: q = Wl2 . p1 + wl4
        const float* row = Wl2 + (size_t)r * 256;
        float a = 0.f;
        #pragma unroll
        for (int k = 0; k < 8; k++) a += row[lane + 32 * k] * g_p1[lane + 32 * k];
        #pragma unroll
        for (int o = 16; o > 0; o >>= 1) a += __shfl_xor_sync(0xFFFFFFFFu, a, o);
        if (lane == 0) g_q[r] = a + wl4[r];
    }
    gridbar();
    {   // stage 2: M = Wl1 . q + wl4
        const float* row = Wl1 + (size_t)r * 256;
        float a = 0.f;
        #pragma unroll
        for (int k = 0; k < 8; k++) a += row[lane + 32 * k] * g_q[lane + 32 * k];
        #pragma unroll
        for (int o = 16; o > 0; o >>= 1) a += __shfl_xor_sync(0xFFFFFFFFu, a, o);
        if (lane == 0) g_M[r] = a + wl4[r];
    }
    gridbar();

    if (blockIdx.x != 0) return;

    __shared__ float sM[256];
    __shared__ float sV[512];
    __shared__ float sRed[8];
    int t = tid;

    sM[t] = g_M[t];
    float contrib = bl1[t] * g_q[t] + bl2[t] * g_p1[t] + bl3[t] * wl4[t];
    __syncthreads();
    if (t < 64)
        contrib += b2[t] * (sM[t] + sM[64 + t] + sM[128 + t] + sM[192 + t]);
    #pragma unroll
    for (int o = 16; o > 0; o >>= 1) contrib += __shfl_xor_sync(0xFFFFFFFFu, contrib, o);
    if (lane == 0) sRed[wid] = contrib;

    #pragma unroll
    for (int rep = 0; rep < 2; rep++) {
        int o = t + rep * 256;
        int n = o >> 7, k = o & 127;
        const float4* w4 = (const float4*)(W2 + (size_t)k * 64);
        const float4* m4 = (const float4*)(sM + n * 64);
        float a = 0.f;
        #pragma unroll
        for (int j = 0; j < 16; j++) {
            float4 w = w4[j], mm = m4[j];
            a += w.x * mm.x + w.y * mm.y + w.z * mm.z + w.w * mm.w;
        }
        sV[o] = a;
    }
    __syncthreads();

    float4 wv[8];
    int    nn[8];
    #pragma unroll
    for (int j = 0; j < 8; j++) {
        int rr = wid * 8 + j;
        if (rr < 56)      { wv[j] = ((const float4*)(W1 + (size_t)(rr % 14) * 128))[lane]; nn[j] = rr / 14; }
        else if (rr < 60) { wv[j] = ((const float4*)b1)[lane];                              nn[j] = rr - 56; }
        else              { wv[j] = make_float4(0.f, 0.f, 0.f, 0.f);                        nn[j] = 0; }
    }
    #pragma unroll
    for (int j = 0; j < 8; j++) {
        int rr = wid * 8 + j;
        if (rr < 60) {
            float4 vv = ((const float4*)(sV + nn[j] * 128))[lane];
            float a = wv[j].x * vv.x + wv[j].y * vv.y + wv[j].z * vv.z + wv[j].w * vv.w;
            #pragma unroll
            for (int o = 16; o > 0; o >>= 1) a += __shfl_xor_sync(0xFFFFFFFFu, a, o);
            if (lane == 0) g_TSC[rr] = a;
        } else if (rr == 60 && lane == 0) {
            float c = bl4[0];
            #pragma unroll
            for (int q = 0; q < 8; q++) c += sRed[q];
            g_TSC[60] = c;
        }
    }
}

// ---- main kernel: vectorized shared roundtrip + packed f32x2 compute
#define TPB 128

__global__ __launch_bounds__(TPB, 4)
void gcn_main(const float* __restrict__ x, const int* __restrict__ eidx,
              float* __restrict__ out)
{
    __shared__ float4 sx4[TPB * 15];   // 60 floats/sample (pad 56->60)
    __shared__ int4   se4[TPB * 7];    // 28 ints/sample  (pad 24->28)
    __shared__ float  sT[64];
    int tid = threadIdx.x;

    // ---- stage: fully coalesced global -> shared, all vector ops
    const float4* Xg = (const float4*)x + (size_t)blockIdx.x * TPB * 14;
    const int4*   Eg = (const int4*)eidx + (size_t)blockIdx.x * TPB * 6;
    float4 xv[14];
    int4   ev[6];
    #pragma unroll
    for (int i = 0; i < 14; i++) xv[i] = Xg[i * TPB + tid];
    #pragma unroll
    for (int i = 0; i < 6; i++)  ev[i] = Eg[i * TPB + tid];
    if (tid < 61) sT[tid] = g_TSC[tid];
    #pragma unroll
    for (int i = 0; i < 14; i++) {
        int idx4 = i * TPB + tid;
        int s = idx4 / 14, j = idx4 % 14;
        sx4[s * 15 + j] = xv[i];               // STS.128, ~conflict-free
    }
    #pragma unroll
    for (int i = 0; i < 6; i++) {
        int i4 = i * TPB + tid;
        int s = i4 / 6, r = i4 % 6;
        se4[s * 7 + r] = ev[i];                // STS.128
    }
    __syncthreads();

    // ---- edges: 6 LDS.128 (stride 112B -> conflict-free), then reg-only hist
    const int4* me4 = se4 + tid * 7;
    int4 f0 = me4[0], f1 = me4[1], f2 = me4[2];
    int4 f3 = me4[3], f4 = me4[4], f5 = me4[5];
    int es[12] = {f0.x,f0.y,f0.z,f0.w, f1.x,f1.y,f1.z,f1.w, f2.x,f2.y,f2.z,f2.w};
    int ed[12] = {f3.x,f3.y,f3.z,f3.w, f4.x,f4.y,f4.z,f4.w, f5.x,f5.y,f5.z,f5.w};

    unsigned h0 = 1u + (1u << 20);         // self loops: codes 0, 5
    unsigned h1 = (1u << 8) + (1u << 28);  // codes 10, 15
    #pragma unroll
    for (int e = 0; e < 12; e++) {
        int code = (ed[e] << 2) | es[e];
        unsigned inc = 1u << ((code & 7) << 2);
        if (code & 8) h1 += inc; else h0 += inc;
    }
    float c[16];
    #pragma unroll
    for (int qd = 0; qd < 8; qd++) {
        c[qd]     = (float)((h0 >> (qd * 4)) & 15u);
        c[qd + 8] = (float)((h1 >> (qd * 4)) & 15u);
    }
    float dinv[4];
    #pragma unroll
    for (int d = 0; d < 4; d++)
        dinv[d] = rsqrtf(c[4*d] + c[4*d+1] + c[4*d+2] + c[4*d+3]);
    float A[16];
    #pragma unroll
    for (int d = 0; d < 4; d++)
        #pragma unroll
        for (int s = 0; s < 4; s++)
            A[d*4+s] = c[d*4+s] * dinv[d] * dinv[s];
    float A2[16], R[4];
    #pragma unroll
    for (int n = 0; n < 4; n++) {
        R[n] = A[n*4] + A[n*4+1] + A[n*4+2] + A[n*4+3];
        #pragma unroll
        for (int p = 0; p < 4; p++) {
            A2[n*4+p] = A[n*4+0] * A[0*4+p] + A[n*4+1] * A[1*4+p]
                      + A[n*4+2] * A[2*4+p] + A[n*4+3] * A[3*4+p];
        }
    }

    // ---- x: 14 LDS.128 (stride 240B -> conflict-free)
    float4 mx4[14];
    const float4* mrow = sx4 + tid * 15;
    #pragma unroll
    for (int j = 0; j < 14; j++) mx4[j] = mrow[j];

    // ---- d2[p*4+n] = x_p . t_n over feature pairs, packed f32x2 FMA
    unsigned long long d2[16];
    #pragma unroll
    for (int i = 0; i < 16; i++) d2[i] = 0ULL;
    #pragma unroll
    for (int q = 0; q < 7; q++) {
        unsigned long long xp[4], tp[4];
        #pragma unroll
        for (int p = 0; p < 4; p++) {
            int off = p * 14 + 2 * q;            // always even -> pair within one float4
            float4 v = mx4[off >> 2];
            xp[p] = (off & 2) ? pack2(v.z, v.w) : pack2(v.x, v.y);
        }
        #pragma unroll
        for (int n = 0; n < 4; n++)
            tp[n] = *(const unsigned long long*)(sT + n * 14 + 2 * q);  // 8B-aligned LDS.64
        #pragma unroll
        for (int p = 0; p < 4; p++)
            #pragma unroll
            for (int n = 0; n < 4; n++)
                fma2(d2[p*4+n], xp[p], tp[n]);
    }

    float acc = sT[60] + R[0]*sT[56] + R[1]*sT[57] + R[2]*sT[58] + R[3]*sT[59];
    #pragma unroll
    for (int n = 0; n < 4; n++)
        #pragma unroll
        for (int p = 0; p < 4; p++)
            acc += A2[n*4+p] * unpack_sum(d2[p*4+n]);

    out[blockIdx.x * TPB + tid] = acc;
}

extern "C" void kernel_launch(void* const* d_in, const int* in_sizes, int n_in,
                              void* d_out, int out_size)
{
    const float* x   = (const float*)d_in[0];
    const int*   ei  = (const int*)  d_in[1];
    const float* W1  = (const float*)d_in[2];
    const float* b1  = (const float*)d_in[3];
    const float* W2  = (const float*)d_in[4];
    const float* b2  = (const float*)d_in[5];
    const float* Wl1 = (const float*)d_in[6];
    const float* bl1 = (const float*)d_in[7];
    const float* Wl2 = (const float*)d_in[8];
    const float* bl2 = (const float*)d_in[9];
    const float* Wl3 = (const float*)d_in[10];
    const float* bl3 = (const float*)d_in[11];
    const float* wl4 = (const float*)d_in[12];
    const float* bl4 = (const float*)d_in[13];

    int B = in_sizes[0] / 56;   // 262144

    precompute<<<32, 256>>>(W1, b1, W2, b2, Wl1, bl1, Wl2, bl2, Wl3, bl3, wl4, bl4);
    gcn_main<<<B / TPB, TPB>>>(x, ei, (float*)d_out);
}